// round 8
// baseline (speedup 1.0000x reference)
#include <cuda_runtime.h>
#include <cstdint>

// ViT patch embedding, mma.sync tf32. M=25088, N=768, K=768 fused with
// patchify + bias + cls. Block tile 128x256, BK=32, warp grid 2(m)x4(n),
// warp tile 64x64, 256 threads, 1 block/SM. 3-stage cp.async ring,
// 32B-rotation swizzle (conflict-free STS16 + LDS.64 frag reads).
// R7: explicit fragment double-buffering — ks+1 frag LDS issued under ks HMMAs.

#define NPATCH  196
#define NIMG    128
#define KDIM    768
#define NDIM    768
#define MTOT    25088

#define BM 128
#define BN 256
#define BK 32
#define NITER (KDIM / BK)            // 24
#define ASTAGE_B 16384               // 128 rows x 128B
#define BSTAGE_B 32768               // 256 rows x 128B
#define STAGE_BYTES (ASTAGE_B + BSTAGE_B)   // 48KB
#define NSTG 3
#define SMEM_BYTES (NSTG * STAGE_BYTES)     // 147456

__device__ float W_pre[NDIM * KDIM];

__device__ __forceinline__ void mma_tf32(float* c, const uint32_t* a, const uint32_t* b) {
    asm volatile(
        "mma.sync.aligned.m16n8k8.row.col.f32.tf32.tf32.f32 "
        "{%0,%1,%2,%3}, {%4,%5,%6,%7}, {%8,%9}, {%0,%1,%2,%3};\n"
        : "+f"(c[0]), "+f"(c[1]), "+f"(c[2]), "+f"(c[3])
        : "r"(a[0]), "r"(a[1]), "r"(a[2]), "r"(a[3]), "r"(b[0]), "r"(b[1]));
}
__device__ __forceinline__ void cp16(uint32_t s, const void* g) {
    asm volatile("cp.async.cg.shared.global [%0], [%1], 16;\n" :: "r"(s), "l"(g));
}
__device__ __forceinline__ void cp_commit() { asm volatile("cp.async.commit_group;\n"); }
template <int N>
__device__ __forceinline__ void cp_wait() { asm volatile("cp.async.wait_group %0;\n" :: "n"(N)); }

__global__ void round_w(const float* __restrict__ W) {
    int i = blockIdx.x * 256 + threadIdx.x;
    if (i < NDIM * KDIM) {
        uint32_t r;
        asm("cvt.rna.tf32.f32 %0, %1;" : "=r"(r) : "f"(W[i]));
        W_pre[i] = __uint_as_float(r);
    }
}

__global__ __launch_bounds__(256, 1) void vit_gemm(
    const float* __restrict__ images,
    const float* __restrict__ bias,
    const float* __restrict__ cls,
    float* __restrict__ out)
{
    extern __shared__ __align__(16) char smc[];

    const int tid  = threadIdx.x;
    const int lane = tid & 31;
    const int warp = tid >> 5;          // 0..7
    const int wm   = warp & 1;          // 2 m-positions of 64
    const int wn   = warp >> 1;         // 4 n-positions of 64
    const int g    = lane >> 2;         // 0..7
    const int tg   = lane & 3;          // 0..3

    const int bm = blockIdx.y * BM;
    const int bn = blockIdx.x * BN;

    // ---------------- loader mapping (quarter-warp = one 128B row) ----------------
    const int lq = lane >> 3;           // 0..3
    const int lc = lane & 7;            // chunk 0..7
    const uint32_t swoff = (uint32_t)((16 * lc + 32 * lq) & 127);

    const float* asrc[4];
    #pragma unroll
    for (int i = 0; i < 4; ++i) {
        const int r   = 16 * warp + 4 * i + lq;
        const int m   = bm + r;
        const int img = m / NPATCH;
        const int pch = m - img * NPATCH;
        const int Pi  = pch / 14;
        const int Pj  = pch - Pi * 14;
        asrc[i] = images + (size_t)img * 150528 + (size_t)(Pi * 16 + (lc >> 2)) * 224
                         + Pj * 16 + (lc & 3) * 4;
    }
    const uint32_t sts_a0 = (uint32_t)(16 * warp + lq) * 128u + swoff;

    const float* bsrc0 = W_pre + (size_t)(bn + 32 * warp + lq) * KDIM + 4 * lc;
    const uint32_t sts_b0 = (uint32_t)(32 * warp + lq) * 128u + swoff;

    const uint32_t sbase = (uint32_t)__cvta_generic_to_shared(smc);

    auto load_tile = [&](int it) {
        const int st  = it - (it / NSTG) * NSTG;
        const int k0  = it * BK;
        const int cch = k0 >> 8;
        const int ph0 = (k0 >> 4) & 15;
        const size_t aoff = (size_t)cch * 50176 + (size_t)ph0 * 224;
        const uint32_t sa = sbase + (uint32_t)st * STAGE_BYTES;
        const uint32_t sb = sa + ASTAGE_B;
        #pragma unroll
        for (int i = 0; i < 4; ++i)
            cp16(sa + sts_a0 + i * 512u, asrc[i] + aoff);
        #pragma unroll
        for (int i = 0; i < 8; ++i)
            cp16(sb + sts_b0 + i * 512u, bsrc0 + i * 3072 + k0);
    };

    float acc[4][8][4];
    #pragma unroll
    for (int mt = 0; mt < 4; ++mt)
        #pragma unroll
        for (int nt = 0; nt < 8; ++nt)
            #pragma unroll
            for (int r = 0; r < 4; ++r) acc[mt][nt][r] = 0.f;

    load_tile(0); cp_commit();
    load_tile(1); cp_commit();

    const uint32_t fr_rot = (uint32_t)(32 * (g & 3));

    // fragment double buffers
    uint32_t af[2][4][4], bf[2][8][2];

    for (int it = 0; it < NITER; ++it) {
        if (it == NITER - 1) cp_wait<0>(); else cp_wait<1>();
        __syncthreads();

        const int st = it - (it / NSTG) * NSTG;
        const char* Ab = smc + st * STAGE_BYTES + (size_t)(wm * 64 + g) * 128;
        const char* Bb = smc + st * STAGE_BYTES + ASTAGE_B + (size_t)(wn * 64 + g) * 128;

        // prime ks=0 fragments into buffer 0
        {
            const uint32_t swz = (uint32_t)((8 * tg + fr_rot) & 127);
            #pragma unroll
            for (int mt = 0; mt < 4; ++mt) {
                const float2 v0 = *reinterpret_cast<const float2*>(Ab + mt * 2048 + swz);
                const float2 v1 = *reinterpret_cast<const float2*>(Ab + mt * 2048 + 1024 + swz);
                af[0][mt][0] = __float_as_uint(v0.x);
                af[0][mt][2] = __float_as_uint(v0.y);
                af[0][mt][1] = __float_as_uint(v1.x);
                af[0][mt][3] = __float_as_uint(v1.y);
            }
            #pragma unroll
            for (int nt = 0; nt < 8; ++nt) {
                const float2 v = *reinterpret_cast<const float2*>(Bb + nt * 1024 + swz);
                bf[0][nt][0] = __float_as_uint(v.x);
                bf[0][nt][1] = __float_as_uint(v.y);
            }
        }

        #pragma unroll
        for (int ks = 0; ks < 4; ++ks) {
            const int cur = ks & 1;
            // prefetch ks+1 fragments into the other buffer (issued before HMMAs)
            if (ks < 3) {
                const int nxt = cur ^ 1;
                const uint32_t swz = (uint32_t)((32 * (ks + 1) + 8 * tg + fr_rot) & 127);
                #pragma unroll
                for (int mt = 0; mt < 4; ++mt) {
                    const float2 v0 = *reinterpret_cast<const float2*>(Ab + mt * 2048 + swz);
                    const float2 v1 = *reinterpret_cast<const float2*>(Ab + mt * 2048 + 1024 + swz);
                    af[nxt][mt][0] = __float_as_uint(v0.x);
                    af[nxt][mt][2] = __float_as_uint(v0.y);
                    af[nxt][mt][1] = __float_as_uint(v1.x);
                    af[nxt][mt][3] = __float_as_uint(v1.y);
                }
                #pragma unroll
                for (int nt = 0; nt < 8; ++nt) {
                    const float2 v = *reinterpret_cast<const float2*>(Bb + nt * 1024 + swz);
                    bf[nxt][nt][0] = __float_as_uint(v.x);
                    bf[nxt][nt][1] = __float_as_uint(v.y);
                }
            }
            if (ks == 0 && it + 2 < NITER) { load_tile(it + 2); cp_commit(); }

            #pragma unroll
            for (int mt = 0; mt < 4; ++mt)
                #pragma unroll
                for (int nt = 0; nt < 8; ++nt)
                    mma_tf32(acc[mt][nt], af[cur][mt], bf[cur][nt]);
        }
    }

    // ---------------- epilogue: bias + scatter ----------------
    float bv[8][2];
    #pragma unroll
    for (int nt = 0; nt < 8; ++nt) {
        const int col = bn + wn * 64 + nt * 8 + tg * 2;
        bv[nt][0] = bias[col];
        bv[nt][1] = bias[col + 1];
    }

    #pragma unroll
    for (int mt = 0; mt < 4; ++mt) {
        #pragma unroll
        for (int rh = 0; rh < 2; ++rh) {
            const int m     = bm + wm * 64 + mt * 16 + rh * 8 + g;
            const int img   = m / NPATCH;
            const int patch = m - img * NPATCH;
            float* orow = out + ((size_t)img * 197 + patch + 1) * NDIM;
            #pragma unroll
            for (int nt = 0; nt < 8; ++nt) {
                const int col = bn + wn * 64 + nt * 8 + tg * 2;
                float2 v;
                v.x = acc[mt][nt][rh * 2 + 0] + bv[nt][0];
                v.y = acc[mt][nt][rh * 2 + 1] + bv[nt][1];
                *reinterpret_cast<float2*>(orow + col) = v;
            }
        }
    }

    // ---------------- fused CLS rows ----------------
    if (blockIdx.y == 0) {
        const int gid = blockIdx.x * 256 + tid;            // 0..767
        const float4* c4 = (const float4*)cls;
        for (int i = gid; i < NIMG * (NDIM / 4); i += 768) {
            const int img = i / (NDIM / 4);
            const int n4  = i - img * (NDIM / 4);
            reinterpret_cast<float4*>(out + (size_t)img * 197 * NDIM)[n4] = c4[n4];
        }
    }
}

extern "C" void kernel_launch(void* const* d_in, const int* in_sizes, int n_in,
                              void* d_out, int out_size) {
    const float* images = (const float*)d_in[0];
    const float* W      = (const float*)d_in[1];
    const float* b      = (const float*)d_in[2];
    const float* cls    = (const float*)d_in[3];
    float* out          = (float*)d_out;

    cudaFuncSetAttribute(vit_gemm, cudaFuncAttributeMaxDynamicSharedMemorySize, SMEM_BYTES);

    round_w<<<(NDIM * KDIM + 255) / 256, 256>>>(W);
    dim3 grid(NDIM / BN, MTOT / BM);   // (3, 196), n fastest for A L2 reuse
    vit_gemm<<<grid, 256, SMEM_BYTES>>>(images, b, cls, out);
}

// round 9
// speedup vs baseline: 1.1843x; 1.1843x over previous
#include <cuda_runtime.h>
#include <cstdint>

// ViT patch embedding, mma.sync tf32. M=25088, N=768, K=768 fused with
// patchify + bias + cls. Block tile 128x256, BK=64 (two 128B k-halves/row),
// warp grid 2(m)x4(n), warp tile 64x64, 256 threads, 1 block/SM.
// 2-stage cp.async ring (192KB smem), 12 iters/12 syncs. 32B-rotation swizzle
// per k-half: conflict-free STS16 + LDS.64 frag reads (k-pair slot permutation).

#define NPATCH  196
#define NIMG    128
#define KDIM    768
#define NDIM    768
#define MTOT    25088

#define BM 128
#define BN 256
#define BK 64
#define NITER (KDIM / BK)            // 12
#define AROW_B 256                   // bytes per A row (BK floats)
#define ASTAGE_B (BM * AROW_B)       // 32768
#define BSTAGE_B (BN * AROW_B)       // 65536
#define STAGE_BYTES (ASTAGE_B + BSTAGE_B)   // 98304
#define SMEM_BYTES (2 * STAGE_BYTES)        // 196608

__device__ float W_pre[NDIM * KDIM];

__device__ __forceinline__ void mma_tf32(float* c, const uint32_t* a, const uint32_t* b) {
    asm volatile(
        "mma.sync.aligned.m16n8k8.row.col.f32.tf32.tf32.f32 "
        "{%0,%1,%2,%3}, {%4,%5,%6,%7}, {%8,%9}, {%0,%1,%2,%3};\n"
        : "+f"(c[0]), "+f"(c[1]), "+f"(c[2]), "+f"(c[3])
        : "r"(a[0]), "r"(a[1]), "r"(a[2]), "r"(a[3]), "r"(b[0]), "r"(b[1]));
}
__device__ __forceinline__ void cp16(uint32_t s, const void* g) {
    asm volatile("cp.async.cg.shared.global [%0], [%1], 16;\n" :: "r"(s), "l"(g));
}
__device__ __forceinline__ void cp_commit() { asm volatile("cp.async.commit_group;\n"); }
template <int N>
__device__ __forceinline__ void cp_wait() { asm volatile("cp.async.wait_group %0;\n" :: "n"(N)); }

__global__ void round_w(const float* __restrict__ W) {
    int i = blockIdx.x * 256 + threadIdx.x;
    if (i < NDIM * KDIM) {
        uint32_t r;
        asm("cvt.rna.tf32.f32 %0, %1;" : "=r"(r) : "f"(W[i]));
        W_pre[i] = __uint_as_float(r);
    }
}

__global__ __launch_bounds__(256, 1) void vit_gemm(
    const float* __restrict__ images,
    const float* __restrict__ bias,
    const float* __restrict__ cls,
    float* __restrict__ out)
{
    extern __shared__ __align__(16) char smc[];

    const int tid  = threadIdx.x;
    const int lane = tid & 31;
    const int warp = tid >> 5;          // 0..7
    const int wm   = warp & 1;          // 2 m-positions of 64
    const int wn   = warp >> 1;         // 4 n-positions of 64
    const int g    = lane >> 2;         // 0..7
    const int tg   = lane & 3;          // 0..3

    const int bm = blockIdx.y * BM;
    const int bn = blockIdx.x * BN;

    // ---------------- loader mapping ----------------
    // quarter-warp lq = row slot, lc = 16B chunk within a 128B k-half.
    const int lq = lane >> 3;           // 0..3
    const int lc = lane & 7;            // 0..7
    const uint32_t swoff = (uint32_t)((16 * lc + 32 * lq) & 127);

    // A rows: 16*warp + 4i + lq (i=0..3); k-half h adds 2 pixel rows (+448 floats)
    const float* asrc[4];
    #pragma unroll
    for (int i = 0; i < 4; ++i) {
        const int r   = 16 * warp + 4 * i + lq;
        const int m   = bm + r;
        const int img = m / NPATCH;
        const int pch = m - img * NPATCH;
        const int Pi  = pch / 14;
        const int Pj  = pch - Pi * 14;
        asrc[i] = images + (size_t)img * 150528 + (size_t)(Pi * 16 + (lc >> 2)) * 224
                         + Pj * 16 + (lc & 3) * 4;
    }
    const uint32_t sts_a0 = (uint32_t)(16 * warp + lq) * AROW_B + swoff;

    // B rows: 32*warp + 4i + lq (i=0..7)
    const float* bsrc0 = W_pre + (size_t)(bn + 32 * warp + lq) * KDIM + 4 * lc;
    const uint32_t sts_b0 = (uint32_t)(32 * warp + lq) * AROW_B + swoff;

    const uint32_t sbase = (uint32_t)__cvta_generic_to_shared(smc);

    auto load_tile = [&](int it) {
        const int st = it & 1;
        // k0 = it*64: channel = it>>2, patch-row base = (it&3)*4
        const size_t aoff = (size_t)(it >> 2) * 50176 + (size_t)((it & 3) * 4) * 224;
        const int k0 = it * BK;
        const uint32_t sa = sbase + (uint32_t)st * STAGE_BYTES;
        const uint32_t sb = sa + ASTAGE_B;
        #pragma unroll
        for (int i = 0; i < 4; ++i)
            #pragma unroll
            for (int h = 0; h < 2; ++h)
                cp16(sa + sts_a0 + i * (4 * AROW_B) + h * 128u,
                     asrc[i] + aoff + h * 448);
        #pragma unroll
        for (int i = 0; i < 8; ++i)
            #pragma unroll
            for (int h = 0; h < 2; ++h)
                cp16(sb + sts_b0 + i * (4 * AROW_B) + h * 128u,
                     bsrc0 + i * (4 * KDIM) + k0 + h * 32);
    };

    float acc[4][8][4];
    #pragma unroll
    for (int mt = 0; mt < 4; ++mt)
        #pragma unroll
        for (int nt = 0; nt < 8; ++nt)
            #pragma unroll
            for (int r = 0; r < 4; ++r) acc[mt][nt][r] = 0.f;

    load_tile(0); cp_commit();

    const uint32_t fr_rot = (uint32_t)(32 * (g & 3));

    for (int it = 0; it < NITER; ++it) {
        __syncthreads();                 // all warps done reading stage (it+1)&1
        if (it + 1 < NITER) { load_tile(it + 1); cp_commit(); cp_wait<1>(); }
        else                { cp_wait<0>(); }
        __syncthreads();                 // stage it visible to all warps

        const int st = it & 1;
        const char* Ab = smc + st * STAGE_BYTES + (size_t)(wm * 64 + g) * AROW_B;
        const char* Bb = smc + st * STAGE_BYTES + ASTAGE_B + (size_t)(wn * 64 + g) * AROW_B;

        #pragma unroll
        for (int ks = 0; ks < 8; ++ks) {
            const uint32_t swz = (uint32_t)(128 * (ks >> 2))
                               + (uint32_t)((32 * (ks & 3) + 8 * tg + fr_rot) & 127);
            uint32_t af[4][4], bf[8][2];
            #pragma unroll
            for (int mt = 0; mt < 4; ++mt) {
                const float2 v0 = *reinterpret_cast<const float2*>(Ab + mt * (16 * AROW_B) + swz);
                const float2 v1 = *reinterpret_cast<const float2*>(Ab + mt * (16 * AROW_B) + 8 * AROW_B + swz);
                af[mt][0] = __float_as_uint(v0.x);   // k = 2tg   (slot tg)
                af[mt][2] = __float_as_uint(v0.y);   // k = 2tg+1 (slot tg+4)
                af[mt][1] = __float_as_uint(v1.x);
                af[mt][3] = __float_as_uint(v1.y);
            }
            #pragma unroll
            for (int nt = 0; nt < 8; ++nt) {
                const float2 v = *reinterpret_cast<const float2*>(Bb + nt * (8 * AROW_B) + swz);
                bf[nt][0] = __float_as_uint(v.x);
                bf[nt][1] = __float_as_uint(v.y);
            }
            #pragma unroll
            for (int mt = 0; mt < 4; ++mt)
                #pragma unroll
                for (int nt = 0; nt < 8; ++nt)
                    mma_tf32(acc[mt][nt], af[mt], bf[nt]);
        }
    }

    // ---------------- epilogue: bias + scatter ----------------
    float bv[8][2];
    #pragma unroll
    for (int nt = 0; nt < 8; ++nt) {
        const int col = bn + wn * 64 + nt * 8 + tg * 2;
        bv[nt][0] = bias[col];
        bv[nt][1] = bias[col + 1];
    }

    #pragma unroll
    for (int mt = 0; mt < 4; ++mt) {
        #pragma unroll
        for (int rh = 0; rh < 2; ++rh) {
            const int m     = bm + wm * 64 + mt * 16 + rh * 8 + g;
            const int img   = m / NPATCH;
            const int patch = m - img * NPATCH;
            float* orow = out + ((size_t)img * 197 + patch + 1) * NDIM;
            #pragma unroll
            for (int nt = 0; nt < 8; ++nt) {
                const int col = bn + wn * 64 + nt * 8 + tg * 2;
                float2 v;
                v.x = acc[mt][nt][rh * 2 + 0] + bv[nt][0];
                v.y = acc[mt][nt][rh * 2 + 1] + bv[nt][1];
                *reinterpret_cast<float2*>(orow + col) = v;
            }
        }
    }

    // ---------------- fused CLS rows ----------------
    if (blockIdx.y == 0) {
        const int gid = blockIdx.x * 256 + tid;            // 0..767
        const float4* c4 = (const float4*)cls;
        for (int i = gid; i < NIMG * (NDIM / 4); i += 768) {
            const int img = i / (NDIM / 4);
            const int n4  = i - img * (NDIM / 4);
            reinterpret_cast<float4*>(out + (size_t)img * 197 * NDIM)[n4] = c4[n4];
        }
    }
}

extern "C" void kernel_launch(void* const* d_in, const int* in_sizes, int n_in,
                              void* d_out, int out_size) {
    const float* images = (const float*)d_in[0];
    const float* W      = (const float*)d_in[1];
    const float* b      = (const float*)d_in[2];
    const float* cls    = (const float*)d_in[3];
    float* out          = (float*)d_out;

    cudaFuncSetAttribute(vit_gemm, cudaFuncAttributeMaxDynamicSharedMemorySize, SMEM_BYTES);

    round_w<<<(NDIM * KDIM + 255) / 256, 256>>>(W);
    dim3 grid(NDIM / BN, MTOT / BM);   // (3, 196), n fastest for A L2 reuse
    vit_gemm<<<grid, 256, SMEM_BYTES>>>(images, b, cls, out);
}

// round 10
// speedup vs baseline: 1.8088x; 1.5273x over previous
#include <cuda_runtime.h>
#include <cuda_fp16.h>
#include <cstdint>

// ViT patch embedding, fp16 mma.sync m16n8k16 (2x FLOP/instr vs tf32 k8).
// Prepass: patchify+convert images -> A_pre[25088][768] fp16; W -> fp16.
// GEMM: block 128x256, BK=64 (128B fp16 rows), warp 64x64, 256 thr, 1 blk/SM,
// 3-stage cp.async ring, ldmatrix.x4 fragments, canonical 128B XOR swizzle.

#define NPATCH  196
#define NIMG    128
#define KDIM    768
#define NDIM    768
#define MTOT    25088

#define BM 128
#define BN 256
#define BK 64
#define NITER (KDIM / BK)              // 12
#define AROW_B 128                     // bytes per row (64 halves)
#define ASTAGE_B (BM * AROW_B)         // 16384
#define BSTAGE_B (BN * AROW_B)         // 32768
#define STAGE_BYTES (ASTAGE_B + BSTAGE_B)   // 49152
#define NSTG 3
#define SMEM_BYTES (NSTG * STAGE_BYTES)     // 147456

__device__ __half A_pre[(size_t)MTOT * KDIM];   // 38.5 MB
__device__ __half W_h[(size_t)NDIM * KDIM];     // 1.18 MB

__device__ __forceinline__ void mma_f16(float* c, const uint32_t* a, const uint32_t* b) {
    asm volatile(
        "mma.sync.aligned.m16n8k16.row.col.f32.f16.f16.f32 "
        "{%0,%1,%2,%3}, {%4,%5,%6,%7}, {%8,%9}, {%0,%1,%2,%3};\n"
        : "+f"(c[0]), "+f"(c[1]), "+f"(c[2]), "+f"(c[3])
        : "r"(a[0]), "r"(a[1]), "r"(a[2]), "r"(a[3]), "r"(b[0]), "r"(b[1]));
}
__device__ __forceinline__ void ldsm4(uint32_t* r, uint32_t addr) {
    asm volatile("ldmatrix.sync.aligned.m8n8.x4.shared.b16 {%0,%1,%2,%3}, [%4];"
                 : "=r"(r[0]), "=r"(r[1]), "=r"(r[2]), "=r"(r[3]) : "r"(addr));
}
__device__ __forceinline__ void cp16(uint32_t s, const void* g) {
    asm volatile("cp.async.cg.shared.global [%0], [%1], 16;\n" :: "r"(s), "l"(g));
}
__device__ __forceinline__ void cp_commit() { asm volatile("cp.async.commit_group;\n"); }
template <int N>
__device__ __forceinline__ void cp_wait() { asm volatile("cp.async.wait_group %0;\n" :: "n"(N)); }

// ---------------- prepass: patchify images -> fp16, W -> fp16 ----------------
#define IMG_WORK (MTOT * 96)            // 8 halves per work item
#define W_WORK   (NDIM * 96)

__global__ void prepass(const float* __restrict__ images, const float* __restrict__ W) {
    const int id = blockIdx.x * 256 + threadIdx.x;
    if (id < IMG_WORK) {
        const int m  = id / 96;
        const int k  = (id - m * 96) * 8;
        const int img = m / NPATCH, pch = m - img * NPATCH;
        const int Pi = pch / 14, Pj = pch - Pi * 14;
        const int c = k >> 8, ph = (k >> 4) & 15, pw = k & 15;
        const float4* s = reinterpret_cast<const float4*>(
            images + (size_t)img * 150528 + (size_t)c * 50176
                   + (size_t)(Pi * 16 + ph) * 224 + Pj * 16 + pw);
        const float4 v0 = s[0], v1 = s[1];
        __half2 h[4];
        h[0] = __floats2half2_rn(v0.x, v0.y);
        h[1] = __floats2half2_rn(v0.z, v0.w);
        h[2] = __floats2half2_rn(v1.x, v1.y);
        h[3] = __floats2half2_rn(v1.z, v1.w);
        *reinterpret_cast<uint4*>(A_pre + (size_t)m * KDIM + k) = *reinterpret_cast<uint4*>(h);
    } else if (id < IMG_WORK + W_WORK) {
        const int id2 = id - IMG_WORK;
        const int n = id2 / 96;
        const int k = (id2 - n * 96) * 8;
        const float4* s = reinterpret_cast<const float4*>(W + (size_t)n * KDIM + k);
        const float4 v0 = s[0], v1 = s[1];
        __half2 h[4];
        h[0] = __floats2half2_rn(v0.x, v0.y);
        h[1] = __floats2half2_rn(v0.z, v0.w);
        h[2] = __floats2half2_rn(v1.x, v1.y);
        h[3] = __floats2half2_rn(v1.z, v1.w);
        *reinterpret_cast<uint4*>(W_h + (size_t)n * KDIM + k) = *reinterpret_cast<uint4*>(h);
    }
}

// ---------------- main GEMM ----------------
__global__ __launch_bounds__(256, 1) void vit_gemm(
    const float* __restrict__ bias,
    const float* __restrict__ cls,
    float* __restrict__ out)
{
    extern __shared__ __align__(16) char smc[];

    const int tid  = threadIdx.x;
    const int lane = tid & 31;
    const int warp = tid >> 5;          // 0..7
    const int wm   = warp & 1;          // 2 m-positions of 64
    const int wn   = warp >> 1;         // 4 n-positions of 64
    const int g    = lane >> 2;         // 0..7
    const int tg   = lane & 3;          // 0..3

    const int bm = blockIdx.y * BM;
    const int bn = blockIdx.x * BN;

    // ---------------- loader mapping (quarter-warp = one 128B row) ----------------
    const int lq = lane >> 3;           // 0..3 row slot
    const int lc = lane & 7;            // 0..7 chunk
    const uint32_t x_even = (uint32_t)((lc ^ lq) << 4);
    const uint32_t x_odd  = (uint32_t)((lc ^ (lq + 4)) << 4);

    const __half* asrc = A_pre + (size_t)(bm + 16 * warp + lq) * KDIM + lc * 8;
    const __half* bsrc = W_h   + (size_t)(bn + 32 * warp + lq) * KDIM + lc * 8;
    const uint32_t sts_a0 = (uint32_t)(16 * warp + lq) * AROW_B;
    const uint32_t sts_b0 = (uint32_t)ASTAGE_B + (uint32_t)(32 * warp + lq) * AROW_B;

    const uint32_t sbase = (uint32_t)__cvta_generic_to_shared(smc);

    auto load_tile = [&](int it) {
        const int st = it - (it / NSTG) * NSTG;
        const int k0 = it * BK;
        const uint32_t sb0 = sbase + (uint32_t)st * STAGE_BYTES;
        #pragma unroll
        for (int i = 0; i < 4; ++i)
            cp16(sb0 + sts_a0 + i * 512u + ((i & 1) ? x_odd : x_even),
                 asrc + (size_t)i * (4 * KDIM) + k0);
        #pragma unroll
        for (int i = 0; i < 8; ++i)
            cp16(sb0 + sts_b0 + i * 512u + ((i & 1) ? x_odd : x_even),
                 bsrc + (size_t)i * (4 * KDIM) + k0);
    };

    float acc[4][8][4];
    #pragma unroll
    for (int mt = 0; mt < 4; ++mt)
        #pragma unroll
        for (int nt = 0; nt < 8; ++nt)
            #pragma unroll
            for (int r = 0; r < 4; ++r) acc[mt][nt][r] = 0.f;

    load_tile(0); cp_commit();
    load_tile(1); cp_commit();

    // ---------------- ldmatrix lane constants ----------------
    const int a_sub = (lane & 7) + ((lane >> 3) & 1) * 8;
    const int chA   = (lane >> 4) & 1;
    const int b_sub = (lane & 7) + ((lane >> 4) & 1) * 8;
    const int chB   = (lane >> 3) & 1;
    const uint32_t lx = (uint32_t)(lane & 7);
    const uint32_t aBase = (uint32_t)(wm * 64 + a_sub) * AROW_B;
    const uint32_t bBase = (uint32_t)ASTAGE_B + (uint32_t)(wn * 64 + b_sub) * AROW_B;

    for (int it = 0; it < NITER; ++it) {
        if (it == NITER - 1) cp_wait<0>(); else cp_wait<1>();
        __syncthreads();

        const int st = it - (it / NSTG) * NSTG;
        const uint32_t stg = sbase + (uint32_t)st * STAGE_BYTES;

        #pragma unroll
        for (int ks = 0; ks < 4; ++ks) {
            uint32_t af[4][4], bf[4][4];
            const uint32_t ach = ((uint32_t)(2 * ks + chA) ^ lx) << 4;
            const uint32_t bch = ((uint32_t)(2 * ks + chB) ^ lx) << 4;
            #pragma unroll
            for (int mt = 0; mt < 4; ++mt)
                ldsm4(af[mt], stg + aBase + mt * 2048u + ach);
            #pragma unroll
            for (int p = 0; p < 4; ++p)
                ldsm4(bf[p], stg + bBase + p * 2048u + bch);

            if (ks == 0 && it + 2 < NITER) { load_tile(it + 2); cp_commit(); }

            #pragma unroll
            for (int mt = 0; mt < 4; ++mt)
                #pragma unroll
                for (int nt = 0; nt < 8; ++nt)
                    mma_f16(acc[mt][nt], af[mt], &bf[nt >> 1][(nt & 1) * 2]);
        }
    }

    // ---------------- epilogue: bias + scatter ----------------
    float bv[8][2];
    #pragma unroll
    for (int nt = 0; nt < 8; ++nt) {
        const int col = bn + wn * 64 + nt * 8 + tg * 2;
        bv[nt][0] = bias[col];
        bv[nt][1] = bias[col + 1];
    }

    #pragma unroll
    for (int mt = 0; mt < 4; ++mt) {
        #pragma unroll
        for (int rh = 0; rh < 2; ++rh) {
            const int m     = bm + wm * 64 + mt * 16 + rh * 8 + g;
            const int img   = m / NPATCH;
            const int patch = m - img * NPATCH;
            float* orow = out + ((size_t)img * 197 + patch + 1) * NDIM;
            #pragma unroll
            for (int nt = 0; nt < 8; ++nt) {
                const int col = bn + wn * 64 + nt * 8 + tg * 2;
                float2 v;
                v.x = acc[mt][nt][rh * 2 + 0] + bv[nt][0];
                v.y = acc[mt][nt][rh * 2 + 1] + bv[nt][1];
                *reinterpret_cast<float2*>(orow + col) = v;
            }
        }
    }

    // ---------------- fused CLS rows ----------------
    if (blockIdx.y == 0) {
        const int gid = blockIdx.x * 256 + tid;            // 0..767
        const float4* c4 = (const float4*)cls;
        for (int i = gid; i < NIMG * (NDIM / 4); i += 768) {
            const int img = i / (NDIM / 4);
            const int n4  = i - img * (NDIM / 4);
            reinterpret_cast<float4*>(out + (size_t)img * 197 * NDIM)[n4] = c4[n4];
        }
    }
}

extern "C" void kernel_launch(void* const* d_in, const int* in_sizes, int n_in,
                              void* d_out, int out_size) {
    const float* images = (const float*)d_in[0];
    const float* W      = (const float*)d_in[1];
    const float* b      = (const float*)d_in[2];
    const float* cls    = (const float*)d_in[3];
    float* out          = (float*)d_out;

    cudaFuncSetAttribute(vit_gemm, cudaFuncAttributeMaxDynamicSharedMemorySize, SMEM_BYTES);

    prepass<<<(IMG_WORK + W_WORK + 255) / 256, 256>>>(images, W);
    dim3 grid(NDIM / BN, MTOT / BM);   // (3, 196), n fastest for A L2 reuse
    vit_gemm<<<grid, 256, SMEM_BYTES>>>(b, cls, out);
}

// round 11
// speedup vs baseline: 1.8098x; 1.0006x over previous
#include <cuda_runtime.h>
#include <cuda_fp16.h>
#include <cstdint>

// ViT patch embedding, fp16 mma.sync m16n8k16.
// R10: 512-thread blocks, tile 256x128, warp tile 64x32 (4 warps/SMSP to break
// barrier phase-lock), acc=64 regs/thread. 3-stage cp.async ring, ldmatrix.x4,
// canonical 128B XOR swizzle. Prepass: warp-per-patch (index math hoisted).

#define NPATCH  196
#define NIMG    128
#define KDIM    768
#define NDIM    768
#define MTOT    25088

#define BM 256
#define BN 128
#define BK 64
#define NITER (KDIM / BK)              // 12
#define AROW_B 128                     // bytes per row (64 halves)
#define ASTAGE_B (BM * AROW_B)         // 32768
#define BSTAGE_B (BN * AROW_B)         // 16384
#define STAGE_BYTES (ASTAGE_B + BSTAGE_B)   // 49152
#define NSTG 3
#define SMEM_BYTES (NSTG * STAGE_BYTES)     // 147456

__device__ __half A_pre[(size_t)MTOT * KDIM];   // 38.5 MB
__device__ __half W_h[(size_t)NDIM * KDIM];     // 1.18 MB

__device__ __forceinline__ void mma_f16(float* c, const uint32_t* a, const uint32_t* b) {
    asm volatile(
        "mma.sync.aligned.m16n8k16.row.col.f32.f16.f16.f32 "
        "{%0,%1,%2,%3}, {%4,%5,%6,%7}, {%8,%9}, {%0,%1,%2,%3};\n"
        : "+f"(c[0]), "+f"(c[1]), "+f"(c[2]), "+f"(c[3])
        : "r"(a[0]), "r"(a[1]), "r"(a[2]), "r"(a[3]), "r"(b[0]), "r"(b[1]));
}
__device__ __forceinline__ void ldsm4(uint32_t* r, uint32_t addr) {
    asm volatile("ldmatrix.sync.aligned.m8n8.x4.shared.b16 {%0,%1,%2,%3}, [%4];"
                 : "=r"(r[0]), "=r"(r[1]), "=r"(r[2]), "=r"(r[3]) : "r"(addr));
}
__device__ __forceinline__ void cp16(uint32_t s, const void* g) {
    asm volatile("cp.async.cg.shared.global [%0], [%1], 16;\n" :: "r"(s), "l"(g));
}
__device__ __forceinline__ void cp_commit() { asm volatile("cp.async.commit_group;\n"); }
template <int N>
__device__ __forceinline__ void cp_wait() { asm volatile("cp.async.wait_group %0;\n" :: "n"(N)); }

// ---------------- prepass: warp-per-patch patchify->fp16; warp-per-row for W ----
#define PRE_BLOCKS ((MTOT + NDIM + 7) / 8)     // 3232 blocks x 8 warps

__global__ __launch_bounds__(256) void prepass(const float* __restrict__ images,
                                               const float* __restrict__ W) {
    const int wg   = blockIdx.x * 8 + (threadIdx.x >> 5);
    const int lane = threadIdx.x & 31;
    if (wg < MTOT) {
        const int m   = wg;
        const int img = m / NPATCH, pch = m - img * NPATCH;
        const int Pi  = pch / 14,   Pj  = pch - Pi * 14;
        // k = p*256 + lane*8  ->  c=p, ph=lane>>1, pw=(lane&1)*8
        const float* src = images + (size_t)img * 150528
                         + (size_t)(Pi * 16 + (lane >> 1)) * 224 + Pj * 16 + (lane & 1) * 8;
        __half* dst = A_pre + (size_t)m * KDIM + lane * 8;
        #pragma unroll
        for (int p = 0; p < 3; ++p) {
            const float4 v0 = *reinterpret_cast<const float4*>(src + (size_t)p * 50176);
            const float4 v1 = *reinterpret_cast<const float4*>(src + (size_t)p * 50176 + 4);
            __half2 h[4];
            h[0] = __floats2half2_rn(v0.x, v0.y);
            h[1] = __floats2half2_rn(v0.z, v0.w);
            h[2] = __floats2half2_rn(v1.x, v1.y);
            h[3] = __floats2half2_rn(v1.z, v1.w);
            *reinterpret_cast<uint4*>(dst + p * 256) = *reinterpret_cast<uint4*>(h);
        }
    } else if (wg < MTOT + NDIM) {
        const int n = wg - MTOT;
        const float* src = W + (size_t)n * KDIM + lane * 8;
        __half* dst = W_h + (size_t)n * KDIM + lane * 8;
        #pragma unroll
        for (int p = 0; p < 3; ++p) {
            const float4 v0 = *reinterpret_cast<const float4*>(src + p * 256);
            const float4 v1 = *reinterpret_cast<const float4*>(src + p * 256 + 4);
            __half2 h[4];
            h[0] = __floats2half2_rn(v0.x, v0.y);
            h[1] = __floats2half2_rn(v0.z, v0.w);
            h[2] = __floats2half2_rn(v1.x, v1.y);
            h[3] = __floats2half2_rn(v1.z, v1.w);
            *reinterpret_cast<uint4*>(dst + p * 256) = *reinterpret_cast<uint4*>(h);
        }
    }
}

// ---------------- main GEMM ----------------
__global__ __launch_bounds__(512, 1) void vit_gemm(
    const float* __restrict__ bias,
    const float* __restrict__ cls,
    float* __restrict__ out)
{
    extern __shared__ __align__(16) char smc[];

    const int tid  = threadIdx.x;
    const int lane = tid & 31;
    const int warp = tid >> 5;          // 0..15
    const int wm   = warp & 3;          // 4 m-positions of 64
    const int wn   = warp >> 2;         // 4 n-positions of 32
    const int g    = lane >> 2;         // 0..7
    const int tg   = lane & 3;          // 0..3

    const int bm = blockIdx.y * BM;
    const int bn = blockIdx.x * BN;

    // ---------------- loader mapping (quarter-warp = one 128B row) ----------------
    const int lq = lane >> 3;           // 0..3 row slot
    const int lc = lane & 7;            // 0..7 chunk
    const uint32_t x_even = (uint32_t)((lc ^ lq) << 4);
    const uint32_t x_odd  = (uint32_t)((lc ^ (lq + 4)) << 4);

    // A: 256 rows = 16 warps x 16 rows, slots i=0..3: row = 16*warp + 4i + lq
    const __half* asrc = A_pre + (size_t)(bm + 16 * warp + lq) * KDIM + lc * 8;
    const uint32_t sts_a0 = (uint32_t)(16 * warp + lq) * AROW_B;
    // B: 128 rows = 16 warps x 8 rows, slots i=0..1: row = 8*warp + 4i + lq
    const __half* bsrc = W_h + (size_t)(bn + 8 * warp + lq) * KDIM + lc * 8;
    const uint32_t sts_b0 = (uint32_t)ASTAGE_B + (uint32_t)(8 * warp + lq) * AROW_B;

    const uint32_t sbase = (uint32_t)__cvta_generic_to_shared(smc);

    auto load_tile = [&](int it) {
        const int st = it - (it / NSTG) * NSTG;
        const int k0 = it * BK;
        const uint32_t sb0 = sbase + (uint32_t)st * STAGE_BYTES;
        #pragma unroll
        for (int i = 0; i < 4; ++i)
            cp16(sb0 + sts_a0 + i * 512u + ((i & 1) ? x_odd : x_even),
                 asrc + (size_t)i * (4 * KDIM) + k0);
        #pragma unroll
        for (int i = 0; i < 2; ++i)
            cp16(sb0 + sts_b0 + i * 512u + ((i & 1) ? x_odd : x_even),
                 bsrc + (size_t)i * (4 * KDIM) + k0);
    };

    float acc[4][4][4];
    #pragma unroll
    for (int mt = 0; mt < 4; ++mt)
        #pragma unroll
        for (int nt = 0; nt < 4; ++nt)
            #pragma unroll
            for (int r = 0; r < 4; ++r) acc[mt][nt][r] = 0.f;

    load_tile(0); cp_commit();
    load_tile(1); cp_commit();

    // ---------------- ldmatrix lane constants (same as R9, verified) ----------------
    const int a_sub = (lane & 7) + ((lane >> 3) & 1) * 8;
    const int chA   = (lane >> 4) & 1;
    const int b_sub = (lane & 7) + ((lane >> 4) & 1) * 8;
    const int chB   = (lane >> 3) & 1;
    const uint32_t lx = (uint32_t)(lane & 7);
    const uint32_t aBase = (uint32_t)(wm * 64 + a_sub) * AROW_B;
    const uint32_t bBase = (uint32_t)ASTAGE_B + (uint32_t)(wn * 32 + b_sub) * AROW_B;

    for (int it = 0; it < NITER; ++it) {
        if (it == NITER - 1) cp_wait<0>(); else cp_wait<1>();
        __syncthreads();

        const int st = it - (it / NSTG) * NSTG;
        const uint32_t stg = sbase + (uint32_t)st * STAGE_BYTES;

        #pragma unroll
        for (int ks = 0; ks < 4; ++ks) {
            uint32_t af[4][4], bf[2][4];
            const uint32_t ach = ((uint32_t)(2 * ks + chA) ^ lx) << 4;
            const uint32_t bch = ((uint32_t)(2 * ks + chB) ^ lx) << 4;
            #pragma unroll
            for (int mt = 0; mt < 4; ++mt)
                ldsm4(af[mt], stg + aBase + mt * 2048u + ach);
            #pragma unroll
            for (int p = 0; p < 2; ++p)
                ldsm4(bf[p], stg + bBase + p * 2048u + bch);

            if (ks == 0 && it + 2 < NITER) { load_tile(it + 2); cp_commit(); }

            #pragma unroll
            for (int mt = 0; mt < 4; ++mt)
                #pragma unroll
                for (int nt = 0; nt < 4; ++nt)
                    mma_f16(acc[mt][nt], af[mt], &bf[nt >> 1][(nt & 1) * 2]);
        }
    }

    // ---------------- epilogue: bias + scatter ----------------
    float bv[4][2];
    #pragma unroll
    for (int nt = 0; nt < 4; ++nt) {
        const int col = bn + wn * 32 + nt * 8 + tg * 2;
        bv[nt][0] = bias[col];
        bv[nt][1] = bias[col + 1];
    }

    #pragma unroll
    for (int mt = 0; mt < 4; ++mt) {
        #pragma unroll
        for (int rh = 0; rh < 2; ++rh) {
            const int m     = bm + wm * 64 + mt * 16 + rh * 8 + g;
            const int img   = m / NPATCH;
            const int patch = m - img * NPATCH;
            float* orow = out + ((size_t)img * 197 + patch + 1) * NDIM;
            #pragma unroll
            for (int nt = 0; nt < 4; ++nt) {
                const int col = bn + wn * 32 + nt * 8 + tg * 2;
                float2 v;
                v.x = acc[mt][nt][rh * 2 + 0] + bv[nt][0];
                v.y = acc[mt][nt][rh * 2 + 1] + bv[nt][1];
                *reinterpret_cast<float2*>(orow + col) = v;
            }
        }
    }

    // ---------------- fused CLS rows ----------------
    if (blockIdx.y == 0) {
        const int gid = blockIdx.x * 512 + tid;            // 0..3071
        const float4* c4 = (const float4*)cls;
        for (int i = gid; i < NIMG * (NDIM / 4); i += 3072) {
            const int img = i / (NDIM / 4);
            const int n4  = i - img * (NDIM / 4);
            reinterpret_cast<float4*>(out + (size_t)img * 197 * NDIM)[n4] = c4[n4];
        }
    }
}

extern "C" void kernel_launch(void* const* d_in, const int* in_sizes, int n_in,
                              void* d_out, int out_size) {
    const float* images = (const float*)d_in[0];
    const float* W      = (const float*)d_in[1];
    const float* b      = (const float*)d_in[2];
    const float* cls    = (const float*)d_in[3];
    float* out          = (float*)d_out;

    cudaFuncSetAttribute(vit_gemm, cudaFuncAttributeMaxDynamicSharedMemorySize, SMEM_BYTES);

    prepass<<<PRE_BLOCKS, 256>>>(images, W);
    dim3 grid(NDIM / BN, MTOT / BM);   // (6, 98), n fastest for A L2 reuse
    vit_gemm<<<grid, 512, SMEM_BYTES>>>(b, cls, out);
}